// round 1
// baseline (speedup 1.0000x reference)
#include <cuda_runtime.h>
#include <cuda_bf16.h>
#include <math.h>

#define Bz 16
#define Sz 256
#define Cz 17
#define Nz 16
#define Dz 32
#define Ez 4
#define Hz 4
#define DHz 8
#define DFFz 64

// ---------------- scratch (static device memory; no allocations) -------------
__device__ float g_xns[Bz * Sz * Nz];              // new_x[:,:, :N]
__device__ float g_q[Bz * Nz * Sz * Dz];
__device__ float g_k[Bz * Nz * Sz * Dz];
__device__ float g_v[Bz * Nz * Sz * Dz];
__device__ int   g_assign[Bz * Sz];
__device__ int   g_lists[Bz * Ez * Sz];
__device__ int   g_counts[Bz * Ez];
__device__ float g_k0[Ez * Dz];
__device__ float g_v0[Ez * Dz];

// ---------------- kernel A: trend + Fourier season + new_x -------------------
// one block per (b, channel c<N); 256 threads (t = time index)
__global__ void preprocess_kernel(const float* __restrict__ x) {
    int blk = blockIdx.x;
    int b = blk / Nz;
    int c = blk % Nz;
    int t = threadIdx.x;

    __shared__ float xs[Sz];
    __shared__ float ctab[Sz], stab[Sz];
    __shared__ float re_s[129], im_s[129], amp_s[129];
    __shared__ float keptre[129], keptim[129];
    __shared__ int   keptf[129];
    __shared__ int   nkept_s;
    __shared__ float thresh_s;

    xs[t] = x[(b * Sz + t) * Cz + c];
    float ang = (float)t / 128.0f;           // 2*pi*t/256 in "pi units"
    ctab[t] = cospif(ang);
    stab[t] = sinpif(ang);
    __syncthreads();

    // direct real DFT: X[f] = sum_t x[t] * exp(-2*pi*i*f*t/256)
    if (t < 129) {
        float re = 0.f, im = 0.f;
        for (int u = 0; u < Sz; u++) {
            int idx = (t * u) & 255;
            float xv = xs[u];
            re += xv * ctab[idx];
            im -= xv * stab[idx];
        }
        re_s[t] = re;
        im_s[t] = im;
        amp_s[t] = sqrtf(re * re + im * im);
    }
    __syncthreads();

    if (t == 0) {
        amp_s[0] = -1e38f;                    // reference sets amp[0] = -inf
        // 4th largest amplitude via 4 destructive max passes on a temp copy
        for (int f = 0; f < 129; f++) keptre[f] = amp_s[f];
        float thr = 0.f;
        for (int pass = 0; pass < 4; pass++) {
            float best = -1e38f; int bi = 0;
            for (int f = 0; f < 129; f++) {
                if (keptre[f] > best) { best = keptre[f]; bi = f; }
            }
            keptre[bi] = -1e38f;
            thr = best;
        }
        thresh_s = thr;
        // compact kept bins (amp >= thresh; bin 0 excluded via -inf)
        int nk = 0;
        for (int f = 0; f < 129; f++) {
            if (amp_s[f] >= thr) {
                keptf[nk] = f;
                keptre[nk] = re_s[f];
                keptim[nk] = im_s[f];
                nk++;
            }
        }
        nkept_s = nk;
    }
    __syncthreads();

    // season[t] = irfft of masked spectrum (only kept bins)
    float season = 0.f;
    int nk = nkept_s;
    for (int j = 0; j < nk; j++) {
        int f = keptf[j];
        float cr = keptre[j], ci = keptim[j];
        int idx = (f * t) & 255;
        if (f == 0)        season += cr;
        else if (f == 128) season += cr * ctab[idx];
        else               season += 2.f * (cr * ctab[idx] - ci * stab[idx]);
    }
    season *= (1.0f / 256.0f);

    // trend: average of moving averages k=4,8,12 (edge-replicated padding ==
    // clamped-index windows t-(k-1)/2 .. t+k/2)
    float s4 = 0.f, s8 = 0.f, s12 = 0.f;
    #pragma unroll
    for (int i = -1; i <= 2; i++) { int u = min(max(t + i, 0), Sz - 1); s4 += xs[u]; }
    #pragma unroll
    for (int i = -3; i <= 4; i++) { int u = min(max(t + i, 0), Sz - 1); s8 += xs[u]; }
    #pragma unroll
    for (int i = -5; i <= 6; i++) { int u = min(max(t + i, 0), Sz - 1); s12 += xs[u]; }
    float trend = (s4 * 0.25f + s8 * 0.125f + s12 * (1.0f / 12.0f)) * (1.0f / 3.0f);

    g_xns[(b * Sz + t) * Nz + c] = xs[t] + season + trend;
}

// ---------------- kernel B: routing + lists + background k0/v0 ---------------
// single block, 256 threads
__global__ void assign_kernel(const float* __restrict__ ox,
                              const float* __restrict__ start_b,
                              const float* __restrict__ ln1_g,
                              const float* __restrict__ ln1_b,
                              const float* __restrict__ Wk,
                              const float* __restrict__ Wv) {
    int t = threadIdx.x;
    __shared__ float red[256];
    __shared__ float smin_s, smax_s;

    float mn = 3.4e38f, mx = -3.4e38f;
    for (int i = t; i < Bz * Sz; i += 256) {
        float s = ox[i * 2 + 1];
        mn = fminf(mn, s);
        mx = fmaxf(mx, s);
    }
    red[t] = mn; __syncthreads();
    for (int o = 128; o > 0; o >>= 1) {
        if (t < o) red[t] = fminf(red[t], red[t + o]);
        __syncthreads();
    }
    if (t == 0) smin_s = red[0];
    __syncthreads();
    red[t] = mx; __syncthreads();
    for (int o = 128; o > 0; o >>= 1) {
        if (t < o) red[t] = fmaxf(red[t], red[t + o]);
        __syncthreads();
    }
    if (t == 0) smax_s = red[0];
    __syncthreads();

    float bmin = smin_s, bmax = smax_s;
    float step = (bmax - bmin) * 0.25f;
    // assign = clip(searchsorted(bins, s, 'right') - 1, 0, E-1)
    //        = clip(#{bins[i] <= s} - 1, 0, E-1)
    for (int i = t; i < Bz * Sz; i += 256) {
        float s = ox[i * 2 + 1];
        int cntb = 0;
        #pragma unroll
        for (int k = 0; k < 5; k++) {
            float bv = bmin + step * (float)k;
            if (bv <= s) cntb++;
        }
        int a = cntb - 1;
        a = max(0, min(Ez - 1, a));
        g_assign[i] = a;
    }
    __syncthreads();

    // per-(b,e) sorted token lists
    if (t < Bz * Ez) {
        int b = t / Ez, e = t % Ez;
        int cnt = 0;
        for (int s = 0; s < Sz; s++)
            if (g_assign[b * Sz + s] == e)
                g_lists[(b * Ez + e) * Sz + cnt++] = s;
        g_counts[b * Ez + e] = cnt;
    }

    // background key/value: unassigned tokens have hidden = start_b (const),
    // so k0_e = LN(start_b; ln1)[e] @ Wk[e], v0_e likewise.
    if (t < Ez * Dz) {
        int e = t / Dz, d = t % Dz;
        float m = 0.f;
        for (int i = 0; i < Dz; i++) m += start_b[i];
        m *= (1.0f / Dz);
        float var = 0.f;
        for (int i = 0; i < Dz; i++) { float dd = start_b[i] - m; var += dd * dd; }
        var *= (1.0f / Dz);
        float rs = rsqrtf(var + 1e-5f);
        float k0 = 0.f, v0 = 0.f;
        for (int i = 0; i < Dz; i++) {
            float z = (start_b[i] - m) * rs * ln1_g[e * Dz + i] + ln1_b[e * Dz + i];
            k0 += z * Wk[(e * Dz + i) * Dz + d];
            v0 += z * Wv[(e * Dz + i) * Dz + d];
        }
        g_k0[e * Dz + d] = k0;
        g_v0[e * Dz + d] = v0;
    }
}

// ---------------- kernel C: per-token LN1 + Q/K/V projections ----------------
// one block per (b,s); 128 threads
__global__ void qkv_kernel(const float* __restrict__ sW,
                           const float* __restrict__ sb,
                           const float* __restrict__ Wq,
                           const float* __restrict__ Wk,
                           const float* __restrict__ Wv,
                           const float* __restrict__ ln1_g,
                           const float* __restrict__ ln1_b) {
    int blk = blockIdx.x;
    int b = blk / Sz, s = blk % Sz;
    int t = threadIdx.x;
    int e = g_assign[b * Sz + s];

    __shared__ float Ws[3][Dz * Dz];
    __shared__ float zs[Nz][Dz];

    const float* Wqe = Wq + e * Dz * Dz;
    const float* Wke = Wk + e * Dz * Dz;
    const float* Wve = Wv + e * Dz * Dz;
    for (int i = t; i < Dz * Dz; i += 128) {
        Ws[0][i] = Wqe[i];
        Ws[1][i] = Wke[i];
        Ws[2][i] = Wve[i];
    }
    if (t < Nz) {
        float a = g_xns[(b * Sz + s) * Nz + t];
        float h[Dz];
        float m = 0.f;
        #pragma unroll
        for (int i = 0; i < Dz; i++) { h[i] = a * sW[i] + sb[i]; m += h[i]; }
        m *= (1.0f / Dz);
        float var = 0.f;
        #pragma unroll
        for (int i = 0; i < Dz; i++) { float d = h[i] - m; var += d * d; }
        var *= (1.0f / Dz);
        float rs = rsqrtf(var + 1e-5f);
        #pragma unroll
        for (int i = 0; i < Dz; i++)
            zs[t][i] = (h[i] - m) * rs * ln1_g[e * Dz + i] + ln1_b[e * Dz + i];
    }
    __syncthreads();

    // 3 mats * 16 n * 32 d = 1536 outputs over 128 threads
    for (int o = t; o < 3 * Nz * Dz; o += 128) {
        int mat = o / (Nz * Dz);
        int r = o % (Nz * Dz);
        int n = r / Dz, d = r % Dz;
        const float* W = Ws[mat];
        float acc = 0.f;
        #pragma unroll
        for (int i = 0; i < Dz; i++) acc += zs[n][i] * W[i * Dz + d];
        float* dst = (mat == 0) ? g_q : ((mat == 1) ? g_k : g_v);
        dst[((b * Nz + n) * Sz + s) * Dz + d] = acc;
    }
}

// ---------------- kernel D: grouped attention + Wo + LN2 + FFN ---------------
// one block per (b, e, n); 256 threads (8 warps); 1 query per warp
__global__ void attn_ffn_kernel(const float* __restrict__ sW,
                                const float* __restrict__ sb,
                                const float* __restrict__ Wo,
                                const float* __restrict__ ln2_g,
                                const float* __restrict__ ln2_b,
                                const float* __restrict__ W1,
                                const float* __restrict__ b1,
                                const float* __restrict__ W2,
                                const float* __restrict__ b2,
                                float* __restrict__ out) {
    int blk = blockIdx.x;
    int b = blk / (Ez * Nz);
    int r = blk % (Ez * Nz);
    int e = r / Nz;
    int n = r % Nz;
    int cnt = g_counts[b * Ez + e];
    if (cnt == 0) return;

    extern __shared__ float smem[];
    float* ks = smem;                 // [cnt][33] padded
    float* vs = smem + cnt * 33;      // [cnt][33]
    const int* lst = &g_lists[(b * Ez + e) * Sz];
    int tid = threadIdx.x;

    for (int idx = tid; idx < cnt * Dz; idx += blockDim.x) {
        int j = idx / Dz, d = idx % Dz;
        int sj = lst[j];
        int gbase = ((b * Nz + n) * Sz + sj) * Dz + d;
        ks[j * 33 + d] = g_k[gbase];
        vs[j * 33 + d] = g_v[gbase];
    }
    __syncthreads();

    int warp = tid / 32, lane = tid % 32;
    const float scale = 0.35355339059327373f;  // 1/sqrt(8)
    const unsigned FULL = 0xffffffffu;
    int nbg = Sz - cnt;
    const float NEG = -1e30f;

    for (int qi = warp; qi < cnt; qi += blockDim.x / 32) {
        int sq = lst[qi];
        float qv[Dz];
        const float* qg = &g_q[((b * Nz + n) * Sz + sq) * Dz];
        #pragma unroll
        for (int i = 0; i < Dz; i++) qv[i] = __ldg(qg + i);

        float m[Hz], den[Hz], o[Hz][DHz];
        #pragma unroll
        for (int h = 0; h < Hz; h++) {
            m[h] = NEG; den[h] = 0.f;
            #pragma unroll
            for (int i = 0; i < DHz; i++) o[h][i] = 0.f;
        }

        // online softmax over this expert's keys; lanes stride over keys
        for (int j = lane; j < cnt; j += 32) {
            const float* kr = &ks[j * 33];
            const float* vr = &vs[j * 33];
            #pragma unroll
            for (int h = 0; h < Hz; h++) {
                float l = 0.f;
                #pragma unroll
                for (int i = 0; i < DHz; i++) l += qv[h * DHz + i] * kr[h * DHz + i];
                l *= scale;
                float mn = fmaxf(m[h], l);
                float sc = __expf(m[h] - mn);
                float w = __expf(l - mn);
                den[h] = den[h] * sc + w;
                #pragma unroll
                for (int i = 0; i < DHz; i++)
                    o[h][i] = o[h][i] * sc + w * vr[h * DHz + i];
                m[h] = mn;
            }
        }

        // cross-lane combine with rescale
        #pragma unroll
        for (int off = 16; off > 0; off >>= 1) {
            #pragma unroll
            for (int h = 0; h < Hz; h++) {
                float m2 = __shfl_xor_sync(FULL, m[h], off);
                float d2 = __shfl_xor_sync(FULL, den[h], off);
                float o2[DHz];
                #pragma unroll
                for (int i = 0; i < DHz; i++) o2[i] = __shfl_xor_sync(FULL, o[h][i], off);
                float mn = fmaxf(m[h], m2);
                float s1 = __expf(m[h] - mn);
                float s2 = __expf(m2 - mn);
                den[h] = den[h] * s1 + d2 * s2;
                #pragma unroll
                for (int i = 0; i < DHz; i++) o[h][i] = o[h][i] * s1 + o2[i] * s2;
                m[h] = mn;
            }
        }

        // background keys: (S - cnt) identical keys k0_e with value v0_e
        if (nbg > 0) {
            #pragma unroll
            for (int h = 0; h < Hz; h++) {
                float l0 = 0.f;
                #pragma unroll
                for (int i = 0; i < DHz; i++)
                    l0 += qv[h * DHz + i] * __ldg(&g_k0[e * Dz + h * DHz + i]);
                l0 *= scale;
                float mn = fmaxf(m[h], l0);
                float s1 = __expf(m[h] - mn);
                float w = __expf(l0 - mn) * (float)nbg;
                den[h] = den[h] * s1 + w;
                #pragma unroll
                for (int i = 0; i < DHz; i++)
                    o[h][i] = o[h][i] * s1 + w * __ldg(&g_v0[e * Dz + h * DHz + i]);
                m[h] = mn;
            }
        }

        float attn[Dz];
        #pragma unroll
        for (int h = 0; h < Hz; h++) {
            float inv = 1.0f / den[h];
            #pragma unroll
            for (int i = 0; i < DHz; i++) attn[h * DHz + i] = o[h][i] * inv;
        }

        // ---- per-token tail, lane-parallel over D dims ----
        float a = g_xns[(b * Sz + sq) * Nz + n];
        float h1 = a * __ldg(&sW[lane]) + __ldg(&sb[lane]);
        const float* Woe = Wo + e * Dz * Dz;
        #pragma unroll
        for (int i = 0; i < Dz; i++) h1 += attn[i] * __ldg(&Woe[i * Dz + lane]);

        // LN2 (two-pass; warp butterfly sums)
        float mu = h1;
        #pragma unroll
        for (int off = 16; off > 0; off >>= 1) mu += __shfl_xor_sync(FULL, mu, off);
        mu *= (1.0f / Dz);
        float df = h1 - mu;
        float var = df * df;
        #pragma unroll
        for (int off = 16; off > 0; off >>= 1) var += __shfl_xor_sync(FULL, var, off);
        var *= (1.0f / Dz);
        float z2 = df * rsqrtf(var + 1e-5f) * __ldg(&ln2_g[e * Dz + lane]) +
                   __ldg(&ln2_b[e * Dz + lane]);

        // FFN: f = relu(z2 @ W1 + b1), out = h1 + f @ W2 + b2
        const float* W1e = W1 + e * Dz * DFFz;
        float f0 = __ldg(&b1[e * DFFz + lane]);
        float f1 = __ldg(&b1[e * DFFz + lane + 32]);
        #pragma unroll
        for (int i = 0; i < Dz; i++) {
            float zi = __shfl_sync(FULL, z2, i);
            f0 += zi * __ldg(&W1e[i * DFFz + lane]);
            f1 += zi * __ldg(&W1e[i * DFFz + lane + 32]);
        }
        f0 = fmaxf(f0, 0.f);
        f1 = fmaxf(f1, 0.f);

        const float* W2e = W2 + e * DFFz * Dz;
        float acc = h1 + __ldg(&b2[e * Dz + lane]);
        #pragma unroll
        for (int j = 0; j < Dz; j++) {
            float fj = __shfl_sync(FULL, f0, j);
            acc += fj * __ldg(&W2e[j * Dz + lane]);
        }
        #pragma unroll
        for (int j = 0; j < Dz; j++) {
            float fj = __shfl_sync(FULL, f1, j);
            acc += fj * __ldg(&W2e[(j + 32) * Dz + lane]);
        }

        out[((b * Sz + sq) * Nz + n) * Dz + lane] = acc;
    }
}

// ---------------- launch ------------------------------------------------------
extern "C" void kernel_launch(void* const* d_in, const int* in_sizes, int n_in,
                              void* d_out, int out_size) {
    const float* x        = (const float*)d_in[0];
    const float* ox       = (const float*)d_in[1];
    const float* start_W  = (const float*)d_in[2];
    const float* start_b  = (const float*)d_in[3];
    const float* Wq       = (const float*)d_in[4];
    const float* Wk       = (const float*)d_in[5];
    const float* Wv       = (const float*)d_in[6];
    const float* Wo       = (const float*)d_in[7];
    const float* ln1_g    = (const float*)d_in[8];
    const float* ln1_b    = (const float*)d_in[9];
    const float* ln2_g    = (const float*)d_in[10];
    const float* ln2_b    = (const float*)d_in[11];
    const float* W1       = (const float*)d_in[12];
    const float* b1       = (const float*)d_in[13];
    const float* W2       = (const float*)d_in[14];
    const float* b2       = (const float*)d_in[15];
    float* out = (float*)d_out;

    int dyn = 2 * Sz * 33 * (int)sizeof(float);  // 67584 bytes
    cudaFuncSetAttribute(attn_ffn_kernel,
                         cudaFuncAttributeMaxDynamicSharedMemorySize, dyn);

    preprocess_kernel<<<Bz * Nz, 256>>>(x);
    assign_kernel<<<1, 256>>>(ox, start_b, ln1_g, ln1_b, Wk, Wv);
    qkv_kernel<<<Bz * Sz, 128>>>(start_W, start_b, Wq, Wk, Wv, ln1_g, ln1_b);
    attn_ffn_kernel<<<Bz * Ez * Nz, 256, dyn>>>(start_W, start_b, Wo, ln2_g,
                                                ln2_b, W1, b1, W2, b2, out);
}

// round 3
// speedup vs baseline: 1.5306x; 1.5306x over previous
#include <cuda_runtime.h>
#include <cuda_bf16.h>
#include <math.h>

#define Bz 16
#define Sz 256
#define Cz 17
#define Nz 16
#define Dz 32
#define Ez 4
#define Hz 4
#define DHz 8
#define DFFz 64

// ---------------- scratch (static device memory; no allocations) -------------
__device__ float g_xns[Bz * Sz * Nz];              // new_x[:,:, :N]
__device__ float g_q[Bz * Nz * Sz * Dz];
__device__ float g_k[Bz * Nz * Sz * Dz];
__device__ float g_v[Bz * Nz * Sz * Dz];
__device__ float g_attn[Bz * Sz * Nz * Dz];        // attention output [b][s][n][d]
__device__ int   g_assign[Bz * Sz];
__device__ int   g_lists[Bz * Ez * Sz];
__device__ int   g_counts[Bz * Ez];
__device__ float g_k0[Ez * Dz];
__device__ float g_v0[Ez * Dz];

// ---------------- kernel A: trend + Fourier season + new_x -------------------
// one block per (b, channel c<N); 256 threads (t = time index)
__global__ void preprocess_kernel(const float* __restrict__ x) {
    int blk = blockIdx.x;
    int b = blk / Nz;
    int c = blk % Nz;
    int t = threadIdx.x;

    __shared__ float xs[Sz];
    __shared__ float ctab[Sz], stab[Sz];
    __shared__ float re_s[129], im_s[129], amp_s[129];
    __shared__ float keptre[129], keptim[129];
    __shared__ int   keptf[129];
    __shared__ int   nkept_s;

    xs[t] = x[(b * Sz + t) * Cz + c];
    float ang = (float)t / 128.0f;           // 2*pi*t/256 in "pi units"
    ctab[t] = cospif(ang);
    stab[t] = sinpif(ang);
    __syncthreads();

    // direct real DFT: X[f] = sum_t x[t] * exp(-2*pi*i*f*t/256)
    if (t < 129) {
        float re = 0.f, im = 0.f;
        for (int u = 0; u < Sz; u++) {
            int idx = (t * u) & 255;
            float xv = xs[u];
            re += xv * ctab[idx];
            im -= xv * stab[idx];
        }
        re_s[t] = re;
        im_s[t] = im;
        amp_s[t] = sqrtf(re * re + im * im);
    }
    __syncthreads();

    if (t == 0) {
        amp_s[0] = -1e38f;                    // reference sets amp[0] = -inf
        // 4th largest amplitude via 4 destructive max passes on a temp copy
        for (int f = 0; f < 129; f++) keptre[f] = amp_s[f];
        float thr = 0.f;
        for (int pass = 0; pass < 4; pass++) {
            float best = -1e38f; int bi = 0;
            for (int f = 0; f < 129; f++) {
                if (keptre[f] > best) { best = keptre[f]; bi = f; }
            }
            keptre[bi] = -1e38f;
            thr = best;
        }
        // compact kept bins (amp >= thresh; bin 0 excluded via -inf)
        int nk = 0;
        for (int f = 0; f < 129; f++) {
            if (amp_s[f] >= thr) {
                keptf[nk] = f;
                keptre[nk] = re_s[f];
                keptim[nk] = im_s[f];
                nk++;
            }
        }
        nkept_s = nk;
    }
    __syncthreads();

    // season[t] = irfft of masked spectrum (only kept bins)
    float season = 0.f;
    int nk = nkept_s;
    for (int j = 0; j < nk; j++) {
        int f = keptf[j];
        float cr = keptre[j], ci = keptim[j];
        int idx = (f * t) & 255;
        if (f == 0)        season += cr;
        else if (f == 128) season += cr * ctab[idx];
        else               season += 2.f * (cr * ctab[idx] - ci * stab[idx]);
    }
    season *= (1.0f / 256.0f);

    // trend: average of moving averages k=4,8,12
    float s4 = 0.f, s8 = 0.f, s12 = 0.f;
    #pragma unroll
    for (int i = -1; i <= 2; i++) { int u = min(max(t + i, 0), Sz - 1); s4 += xs[u]; }
    #pragma unroll
    for (int i = -3; i <= 4; i++) { int u = min(max(t + i, 0), Sz - 1); s8 += xs[u]; }
    #pragma unroll
    for (int i = -5; i <= 6; i++) { int u = min(max(t + i, 0), Sz - 1); s12 += xs[u]; }
    float trend = (s4 * 0.25f + s8 * 0.125f + s12 * (1.0f / 12.0f)) * (1.0f / 3.0f);

    g_xns[(b * Sz + t) * Nz + c] = xs[t] + season + trend;
}

// ---------------- kernel B: routing + lists + background k0/v0 ---------------
__global__ void assign_kernel(const float* __restrict__ ox,
                              const float* __restrict__ start_b,
                              const float* __restrict__ ln1_g,
                              const float* __restrict__ ln1_b,
                              const float* __restrict__ Wk,
                              const float* __restrict__ Wv) {
    int t = threadIdx.x;
    __shared__ float red[256];
    __shared__ float smin_s, smax_s;

    float mn = 3.4e38f, mx = -3.4e38f;
    for (int i = t; i < Bz * Sz; i += 256) {
        float s = ox[i * 2 + 1];
        mn = fminf(mn, s);
        mx = fmaxf(mx, s);
    }
    red[t] = mn; __syncthreads();
    for (int o = 128; o > 0; o >>= 1) {
        if (t < o) red[t] = fminf(red[t], red[t + o]);
        __syncthreads();
    }
    if (t == 0) smin_s = red[0];
    __syncthreads();
    red[t] = mx; __syncthreads();
    for (int o = 128; o > 0; o >>= 1) {
        if (t < o) red[t] = fmaxf(red[t], red[t + o]);
        __syncthreads();
    }
    if (t == 0) smax_s = red[0];
    __syncthreads();

    float bmin = smin_s, bmax = smax_s;
    float step = (bmax - bmin) * 0.25f;
    for (int i = t; i < Bz * Sz; i += 256) {
        float s = ox[i * 2 + 1];
        int cntb = 0;
        #pragma unroll
        for (int k = 0; k < 5; k++) {
            float bv = bmin + step * (float)k;
            if (bv <= s) cntb++;
        }
        int a = cntb - 1;
        a = max(0, min(Ez - 1, a));
        g_assign[i] = a;
    }
    __syncthreads();

    if (t < Bz * Ez) {
        int b = t / Ez, e = t % Ez;
        int cnt = 0;
        for (int s = 0; s < Sz; s++)
            if (g_assign[b * Sz + s] == e)
                g_lists[(b * Ez + e) * Sz + cnt++] = s;
        g_counts[b * Ez + e] = cnt;
    }

    if (t < Ez * Dz) {
        int e = t / Dz, d = t % Dz;
        float m = 0.f;
        for (int i = 0; i < Dz; i++) m += start_b[i];
        m *= (1.0f / Dz);
        float var = 0.f;
        for (int i = 0; i < Dz; i++) { float dd = start_b[i] - m; var += dd * dd; }
        var *= (1.0f / Dz);
        float rs = rsqrtf(var + 1e-5f);
        float k0 = 0.f, v0 = 0.f;
        for (int i = 0; i < Dz; i++) {
            float z = (start_b[i] - m) * rs * ln1_g[e * Dz + i] + ln1_b[e * Dz + i];
            k0 += z * Wk[(e * Dz + i) * Dz + d];
            v0 += z * Wv[(e * Dz + i) * Dz + d];
        }
        g_k0[e * Dz + d] = k0;
        g_v0[e * Dz + d] = v0;
    }
}

// ---------------- kernel C: per-token LN1 + Q/K/V projections ----------------
__global__ void qkv_kernel(const float* __restrict__ sW,
                           const float* __restrict__ sb,
                           const float* __restrict__ Wq,
                           const float* __restrict__ Wk,
                           const float* __restrict__ Wv,
                           const float* __restrict__ ln1_g,
                           const float* __restrict__ ln1_b) {
    int blk = blockIdx.x;
    int b = blk / Sz, s = blk % Sz;
    int t = threadIdx.x;
    int e = g_assign[b * Sz + s];

    __shared__ float Ws[3][Dz * Dz];
    __shared__ float zs[Nz][Dz];

    const float* Wqe = Wq + e * Dz * Dz;
    const float* Wke = Wk + e * Dz * Dz;
    const float* Wve = Wv + e * Dz * Dz;
    for (int i = t; i < Dz * Dz; i += 128) {
        Ws[0][i] = Wqe[i];
        Ws[1][i] = Wke[i];
        Ws[2][i] = Wve[i];
    }
    if (t < Nz) {
        float a = g_xns[(b * Sz + s) * Nz + t];
        float h[Dz];
        float m = 0.f;
        #pragma unroll
        for (int i = 0; i < Dz; i++) { h[i] = a * sW[i] + sb[i]; m += h[i]; }
        m *= (1.0f / Dz);
        float var = 0.f;
        #pragma unroll
        for (int i = 0; i < Dz; i++) { float d = h[i] - m; var += d * d; }
        var *= (1.0f / Dz);
        float rs = rsqrtf(var + 1e-5f);
        #pragma unroll
        for (int i = 0; i < Dz; i++)
            zs[t][i] = (h[i] - m) * rs * ln1_g[e * Dz + i] + ln1_b[e * Dz + i];
    }
    __syncthreads();

    for (int o = t; o < 3 * Nz * Dz; o += 128) {
        int mat = o / (Nz * Dz);
        int r = o % (Nz * Dz);
        int n = r / Dz, d = r % Dz;
        const float* W = Ws[mat];
        float acc = 0.f;
        #pragma unroll
        for (int i = 0; i < Dz; i++) acc += zs[n][i] * W[i * Dz + d];
        float* dst = (mat == 0) ? g_q : ((mat == 1) ? g_k : g_v);
        dst[((b * Nz + n) * Sz + s) * Dz + d] = acc;
    }
}

// ---------------- kernel D: attention (lane = query, two-pass softmax) -------
// one block per (b, e, n); 256 threads (8 warps); 32 queries per warp
__global__ __launch_bounds__(256, 2) void attn_kernel() {
    int blk = blockIdx.x;
    int b = blk / (Ez * Nz);
    int r = blk % (Ez * Nz);
    int e = r / Nz;
    int n = r % Nz;
    int cnt = g_counts[b * Ez + e];
    if (cnt == 0) return;

    extern __shared__ float smem[];
    float* ks = smem;                 // [cnt][32] contiguous rows
    float* vs = smem + cnt * Dz;
    const int* lst = &g_lists[(b * Ez + e) * Sz];
    int tid = threadIdx.x;

    // float4 cooperative load of k/v rows (gathered by token list)
    int nf4 = cnt * 8;
    const float4* gk4 = (const float4*)g_k;
    const float4* gv4 = (const float4*)g_v;
    for (int idx = tid; idx < nf4; idx += blockDim.x) {
        int j = idx >> 3, f = idx & 7;
        int sj = lst[j];
        long base = (long)((b * Nz + n) * Sz + sj) * 8 + f;
        ((float4*)ks)[idx] = gk4[base];
        ((float4*)vs)[idx] = gv4[base];
    }
    __syncthreads();

    int warp = tid >> 5, lane = tid & 31;
    int qi = warp * 32 + lane;
    if (warp * 32 >= cnt) return;
    bool active = qi < cnt;
    int sq = lst[active ? qi : 0];

    const float scale = 0.35355339059327373f;  // 1/sqrt(8)

    // load this lane's query (32 floats)
    float qv[Dz];
    {
        const float4* qg = (const float4*)(g_q + (long)((b * Nz + n) * Sz + sq) * Dz);
        #pragma unroll
        for (int f = 0; f < 8; f++) {
            float4 tq = __ldg(qg + f);
            qv[f * 4 + 0] = tq.x; qv[f * 4 + 1] = tq.y;
            qv[f * 4 + 2] = tq.z; qv[f * 4 + 3] = tq.w;
        }
    }

    // background logit per head (k0 broadcast)
    float l0[Hz];
    #pragma unroll
    for (int h = 0; h < Hz; h++) {
        float l = 0.f;
        #pragma unroll
        for (int i = 0; i < DHz; i++)
            l += qv[h * DHz + i] * __ldg(&g_k0[e * Dz + h * DHz + i]);
        l0[h] = l * scale;
    }

    float m[Hz];
    #pragma unroll
    for (int h = 0; h < Hz; h++) m[h] = l0[h];

    // ---- pass 1: max over keys ----
    for (int j = 0; j < cnt; j++) {
        const float4* kr = (const float4*)(ks + j * Dz);
        #pragma unroll
        for (int h = 0; h < Hz; h++) {
            float4 a = kr[h * 2], c = kr[h * 2 + 1];
            float l = qv[h*8+0]*a.x + qv[h*8+1]*a.y + qv[h*8+2]*a.z + qv[h*8+3]*a.w
                    + qv[h*8+4]*c.x + qv[h*8+5]*c.y + qv[h*8+6]*c.z + qv[h*8+7]*c.w;
            m[h] = fmaxf(m[h], l * scale);
        }
    }

    // ---- pass 2: exp + accumulate (no rescale needed) ----
    float den[Hz], o[Hz][DHz];
    int nbg = Sz - cnt;
    #pragma unroll
    for (int h = 0; h < Hz; h++) {
        float w0 = __expf(l0[h] - m[h]) * (float)nbg;
        den[h] = w0;
        #pragma unroll
        for (int i = 0; i < DHz; i++)
            o[h][i] = w0 * __ldg(&g_v0[e * Dz + h * DHz + i]);
    }

    for (int j = 0; j < cnt; j++) {
        const float4* kr = (const float4*)(ks + j * Dz);
        const float4* vr = (const float4*)(vs + j * Dz);
        #pragma unroll
        for (int h = 0; h < Hz; h++) {
            float4 a = kr[h * 2], c = kr[h * 2 + 1];
            float l = qv[h*8+0]*a.x + qv[h*8+1]*a.y + qv[h*8+2]*a.z + qv[h*8+3]*a.w
                    + qv[h*8+4]*c.x + qv[h*8+5]*c.y + qv[h*8+6]*c.z + qv[h*8+7]*c.w;
            float w = __expf(l * scale - m[h]);
            den[h] += w;
            float4 va = vr[h * 2], vc = vr[h * 2 + 1];
            o[h][0] += w * va.x; o[h][1] += w * va.y;
            o[h][2] += w * va.z; o[h][3] += w * va.w;
            o[h][4] += w * vc.x; o[h][5] += w * vc.y;
            o[h][6] += w * vc.z; o[h][7] += w * vc.w;
        }
    }

    if (active) {
        float4* dst = (float4*)(g_attn + (long)((b * Sz + sq) * Nz + n) * Dz);
        #pragma unroll
        for (int h = 0; h < Hz; h++) {
            float inv = 1.0f / den[h];
            float4 r0 = make_float4(o[h][0]*inv, o[h][1]*inv, o[h][2]*inv, o[h][3]*inv);
            float4 r1 = make_float4(o[h][4]*inv, o[h][5]*inv, o[h][6]*inv, o[h][7]*inv);
            dst[h * 2]     = r0;
            dst[h * 2 + 1] = r1;
        }
    }
}

// ---------------- kernel E: Wo + LN2 + FFN tail ------------------------------
// one block per (b,s); 128 threads (4 warps); each warp handles 4 channels
__global__ __launch_bounds__(128) void tail_kernel(const float* __restrict__ sW,
                                                   const float* __restrict__ sb,
                                                   const float* __restrict__ Wo,
                                                   const float* __restrict__ ln2_g,
                                                   const float* __restrict__ ln2_b,
                                                   const float* __restrict__ W1,
                                                   const float* __restrict__ b1,
                                                   const float* __restrict__ W2,
                                                   const float* __restrict__ b2,
                                                   float* __restrict__ out) {
    int blk = blockIdx.x;                 // token index b*Sz+s
    int e = g_assign[blk];
    int tid = threadIdx.x;
    int warp = tid >> 5, lane = tid & 31;

    __shared__ float attn_s[Nz][Dz];      // 2KB
    __shared__ float xs[Nz];
    __shared__ float z2_s[Nz][Dz];        // 2KB
    __shared__ float f_s[Nz][DFFz];       // 4KB

    {
        const float4* src = (const float4*)(g_attn + (long)blk * Nz * Dz);
        for (int i = tid; i < Nz * Dz / 4; i += 128)
            ((float4*)attn_s)[i] = src[i];
        if (tid < Nz) xs[tid] = g_xns[blk * Nz + tid];
    }
    __syncthreads();

    const unsigned FULL = 0xffffffffu;
    const float sWl = __ldg(&sW[lane]);
    const float sbl = __ldg(&sb[lane]);
    const float g2l = __ldg(&ln2_g[e * Dz + lane]);
    const float b2ln = __ldg(&ln2_b[e * Dz + lane]);
    const float bias2 = __ldg(&b2[e * Dz + lane]);
    const float bias1a = __ldg(&b1[e * DFFz + lane]);
    const float bias1b = __ldg(&b1[e * DFFz + lane + 32]);

    int n0 = warp * 4;
    float h1[4];
    #pragma unroll
    for (int k = 0; k < 4; k++) h1[k] = xs[n0 + k] * sWl + sbl;

    // h1 += attn @ Wo  (Wo LDG amortized over 4 channels)
    const float* Woe = Wo + e * Dz * Dz;
    #pragma unroll
    for (int i = 0; i < Dz; i++) {
        float w = __ldg(&Woe[i * Dz + lane]);
        #pragma unroll
        for (int k = 0; k < 4; k++) h1[k] += attn_s[n0 + k][i] * w;
    }

    // LN2 per channel (warp butterfly over lanes)
    #pragma unroll
    for (int k = 0; k < 4; k++) {
        float mu = h1[k];
        #pragma unroll
        for (int off = 16; off > 0; off >>= 1) mu += __shfl_xor_sync(FULL, mu, off);
        mu *= (1.0f / Dz);
        float df = h1[k] - mu;
        float var = df * df;
        #pragma unroll
        for (int off = 16; off > 0; off >>= 1) var += __shfl_xor_sync(FULL, var, off);
        var *= (1.0f / Dz);
        float z = df * rsqrtf(var + 1e-5f) * g2l + b2ln;
        z2_s[n0 + k][lane] = z;
    }
    __syncwarp();

    // FFN layer 1: f = relu(z2 @ W1 + b1); W1 LDG amortized over 4 channels
    const float* W1e = W1 + e * Dz * DFFz;
    float f0[4], f1[4];
    #pragma unroll
    for (int k = 0; k < 4; k++) { f0[k] = bias1a; f1[k] = bias1b; }
    #pragma unroll
    for (int i = 0; i < Dz; i++) {
        float w0 = __ldg(&W1e[i * DFFz + lane]);
        float w1 = __ldg(&W1e[i * DFFz + lane + 32]);
        #pragma unroll
        for (int k = 0; k < 4; k++) {
            float z = z2_s[n0 + k][i];
            f0[k] += z * w0;
            f1[k] += z * w1;
        }
    }
    #pragma unroll
    for (int k = 0; k < 4; k++) {
        f_s[n0 + k][lane]      = fmaxf(f0[k], 0.f);
        f_s[n0 + k][lane + 32] = fmaxf(f1[k], 0.f);
    }
    __syncwarp();

    // FFN layer 2: out = h1 + f @ W2 + b2; W2 LDG amortized over 4 channels
    const float* W2e = W2 + e * DFFz * Dz;
    float acc[4];
    #pragma unroll
    for (int k = 0; k < 4; k++) acc[k] = h1[k] + bias2;
    #pragma unroll
    for (int j = 0; j < DFFz; j++) {
        float w2 = __ldg(&W2e[j * Dz + lane]);
        #pragma unroll
        for (int k = 0; k < 4; k++) acc[k] += f_s[n0 + k][j] * w2;
    }
    #pragma unroll
    for (int k = 0; k < 4; k++)
        out[((long)blk * Nz + n0 + k) * Dz + lane] = acc[k];
}

// ---------------- launch ------------------------------------------------------
extern "C" void kernel_launch(void* const* d_in, const int* in_sizes, int n_in,
                              void* d_out, int out_size) {
    const float* x        = (const float*)d_in[0];
    const float* ox       = (const float*)d_in[1];
    const float* start_W  = (const float*)d_in[2];
    const float* start_b  = (const float*)d_in[3];
    const float* Wq       = (const float*)d_in[4];
    const float* Wk       = (const float*)d_in[5];
    const float* Wv       = (const float*)d_in[6];
    const float* Wo       = (const float*)d_in[7];
    const float* ln1_g    = (const float*)d_in[8];
    const float* ln1_b    = (const float*)d_in[9];
    const float* ln2_g    = (const float*)d_in[10];
    const float* ln2_b    = (const float*)d_in[11];
    const float* W1       = (const float*)d_in[12];
    const float* b1       = (const float*)d_in[13];
    const float* W2       = (const float*)d_in[14];
    const float* b2       = (const float*)d_in[15];
    float* out = (float*)d_out;

    int dyn = 2 * Sz * Dz * (int)sizeof(float);  // 65536 bytes
    static int attr_set = 0;
    if (!attr_set) {
        cudaFuncSetAttribute(attn_kernel,
                             cudaFuncAttributeMaxDynamicSharedMemorySize, dyn);
        attr_set = 1;
    }

    preprocess_kernel<<<Bz * Nz, 256>>>(x);
    assign_kernel<<<1, 256>>>(ox, start_b, ln1_g, ln1_b, Wk, Wv);
    qkv_kernel<<<Bz * Sz, 128>>>(start_W, start_b, Wq, Wk, Wv, ln1_g, ln1_b);
    attn_kernel<<<Bz * Ez * Nz, 256, dyn>>>();
    tail_kernel<<<Bz * Sz, 128>>>(start_W, start_b, Wo, ln2_g, ln2_b,
                                  W1, b1, W2, b2, out);
}